// round 1
// baseline (speedup 1.0000x reference)
#include <cuda_runtime.h>

#define NB 4
#define NS 2048
#define ND 1024
#define NH 16
#define NHD 64

// Scratch (device globals — allocation-free rule)
__device__ float g_Q[NB*NH*NS*NHD];
__device__ float g_K[NB*NH*NS*NHD];
__device__ float g_V[NB*NH*NS*NHD];
__device__ float g_ctx[NB*NS*ND];

// ---------------------------------------------------------------------------
// SGEMM (NT): C[M,N] = A[M,K] @ W[N,K]^T + bias
// BM=BN=128, BK=16, 256 threads, 8x8 per-thread tile.
// EPI==0: scatter into g_Q/g_K/g_V per the reference reshape.
// EPI==1: C[m*NDIM+n] = val + bias[n].
// ---------------------------------------------------------------------------
template<int KDIM, int EPI, int NDIM>
__global__ void __launch_bounds__(256)
sgemm_nt(const float* __restrict__ A, const float* __restrict__ W,
         const float* __restrict__ bias, float* __restrict__ C)
{
    __shared__ float As[16][128];
    __shared__ float Bs[16][128];

    const int tid = threadIdx.x;
    const int m0 = blockIdx.y * 128;
    const int n0 = blockIdx.x * 128;
    const int ty = tid >> 4;
    const int tx = tid & 15;

    const int lr = tid >> 2;          // 0..63
    const int lc = (tid & 3) << 2;    // 0,4,8,12

    float acc[8][8];
    #pragma unroll
    for (int i = 0; i < 8; i++)
        #pragma unroll
        for (int j = 0; j < 8; j++) acc[i][j] = 0.f;

    const float* Ap0 = A + (size_t)(m0 + lr) * KDIM + lc;
    const float* Ap1 = A + (size_t)(m0 + lr + 64) * KDIM + lc;
    const float* Wp0 = W + (size_t)(n0 + lr) * KDIM + lc;
    const float* Wp1 = W + (size_t)(n0 + lr + 64) * KDIM + lc;

    for (int k0 = 0; k0 < KDIM; k0 += 16) {
        float4 a0 = *(const float4*)(Ap0 + k0);
        float4 a1 = *(const float4*)(Ap1 + k0);
        float4 b0 = *(const float4*)(Wp0 + k0);
        float4 b1 = *(const float4*)(Wp1 + k0);
        As[lc+0][lr]    = a0.x; As[lc+1][lr]    = a0.y; As[lc+2][lr]    = a0.z; As[lc+3][lr]    = a0.w;
        As[lc+0][lr+64] = a1.x; As[lc+1][lr+64] = a1.y; As[lc+2][lr+64] = a1.z; As[lc+3][lr+64] = a1.w;
        Bs[lc+0][lr]    = b0.x; Bs[lc+1][lr]    = b0.y; Bs[lc+2][lr]    = b0.z; Bs[lc+3][lr]    = b0.w;
        Bs[lc+0][lr+64] = b1.x; Bs[lc+1][lr+64] = b1.y; Bs[lc+2][lr+64] = b1.z; Bs[lc+3][lr+64] = b1.w;
        __syncthreads();
        #pragma unroll
        for (int kk = 0; kk < 16; kk++) {
            float ar[8], br[8];
            *(float4*)&ar[0] = *(const float4*)&As[kk][ty*8];
            *(float4*)&ar[4] = *(const float4*)&As[kk][ty*8+4];
            *(float4*)&br[0] = *(const float4*)&Bs[kk][tx*8];
            *(float4*)&br[4] = *(const float4*)&Bs[kk][tx*8+4];
            #pragma unroll
            for (int i = 0; i < 8; i++)
                #pragma unroll
                for (int j = 0; j < 8; j++)
                    acc[i][j] = fmaf(ar[i], br[j], acc[i][j]);
        }
        __syncthreads();
    }

    if (EPI == 0) {
        // qkv scatter: n -> head = n/192, r = n%192; r<64:Q, r<128:K, else V
        #pragma unroll
        for (int i = 0; i < 8; i++) {
            int m = m0 + ty*8 + i;
            int b = m >> 11;          // m / NS
            int s = m & (NS - 1);
            #pragma unroll
            for (int j = 0; j < 8; j++) {
                int n = n0 + tx*8 + j;
                float v = acc[i][j] + bias[n];
                int head = n / 192;
                int r = n - head * 192;
                size_t base = ((size_t)(b*NH + head)*NS + s) * NHD;
                if (r < 64)       g_Q[base + r]       = v;
                else if (r < 128) g_K[base + r - 64]  = v;
                else              g_V[base + r - 128] = v;
            }
        }
    } else {
        #pragma unroll
        for (int i = 0; i < 8; i++) {
            int m = m0 + ty*8 + i;
            #pragma unroll
            for (int v = 0; v < 2; v++) {
                int n = n0 + tx*8 + v*4;
                float4 o;
                o.x = acc[i][v*4+0] + bias[n+0];
                o.y = acc[i][v*4+1] + bias[n+1];
                o.z = acc[i][v*4+2] + bias[n+2];
                o.w = acc[i][v*4+3] + bias[n+3];
                *(float4*)&C[(size_t)m*NDIM + n] = o;
            }
        }
    }
}

// ---------------------------------------------------------------------------
// Flash attention: per CTA one (b,h) and one 64-row Q tile. Online softmax.
// Pad semantics (match reference EXACTLY): softmax denominator over causal
// scores only (no pad); pad[k] folded into V tile (numerator); pad[q] applied
// to the final output row. 48KB smem (KPs buffer shared by K^T and P).
// ---------------------------------------------------------------------------
__global__ void __launch_bounds__(256)
flash_attn(const int* __restrict__ pad, const int* __restrict__ amask)
{
    __shared__ float Qs[64*64];
    __shared__ float KPs[64*64];   // K^T during score phase, P during PV phase
    __shared__ float Vs[64*64];

    const int tid = threadIdx.x;
    const int qt = blockIdx.x;       // 0..31
    const int bh = blockIdx.y;       // 0..63
    const int b  = bh >> 4;
    const int h  = bh & 15;
    const int q0 = qt * 64;
    const int causal = amask ? (amask[0] != 0) : 1;

    const int lr = tid >> 2;          // 0..63 (load row)
    const int lc = (tid & 3) << 4;    // 0,16,32,48 (load col base)

    // Load Q tile [64 rows][64 dims]
    {
        const float* Qg = g_Q + ((size_t)bh*NS + q0 + lr)*NHD + lc;
        #pragma unroll
        for (int v = 0; v < 4; v++)
            *(float4*)&Qs[lr*64 + lc + v*4] = *(const float4*)(Qg + v*4);
    }

    const int ty = tid >> 4, tx = tid & 15;  // 4 rows x 4 cols micro-tile
    float mrow[4], lrow[4], accO[4][4];
    #pragma unroll
    for (int i = 0; i < 4; i++) {
        mrow[i] = -1e30f; lrow[i] = 0.f;
        #pragma unroll
        for (int j = 0; j < 4; j++) accO[i][j] = 0.f;
    }

    const int ktmax = causal ? qt : (NS/64 - 1);
    for (int kt = 0; kt <= ktmax; kt++) {
        const int k0 = kt * 64;
        __syncthreads();  // previous PV done reading KPs/Vs (also covers Q load, tile 0)

        // Load K transposed (KPs[d][c]) and V (pad-folded, Vs[k][d])
        {
            const float* Kg = g_K + ((size_t)bh*NS + k0 + lr)*NHD + lc;
            const float* Vg = g_V + ((size_t)bh*NS + k0 + lr)*NHD + lc;
            const float pk = pad[b*NS + k0 + lr] ? 1.f : 0.f;
            #pragma unroll
            for (int v = 0; v < 4; v++) {
                float4 kk = *(const float4*)(Kg + v*4);
                KPs[(lc+v*4+0)*64 + lr] = kk.x;
                KPs[(lc+v*4+1)*64 + lr] = kk.y;
                KPs[(lc+v*4+2)*64 + lr] = kk.z;
                KPs[(lc+v*4+3)*64 + lr] = kk.w;
                float4 vv = *(const float4*)(Vg + v*4);
                vv.x *= pk; vv.y *= pk; vv.z *= pk; vv.w *= pk;
                *(float4*)&Vs[lr*64 + lc + v*4] = vv;
            }
        }
        __syncthreads();

        // Scores s[4][4] = Q[r] . K[c]
        float s[4][4];
        #pragma unroll
        for (int i = 0; i < 4; i++)
            #pragma unroll
            for (int j = 0; j < 4; j++) s[i][j] = 0.f;

        #pragma unroll
        for (int d = 0; d < 64; d += 4) {
            float4 q4[4];
            float kr[4][4];
            #pragma unroll
            for (int i = 0; i < 4; i++)
                q4[i] = *(const float4*)&Qs[(ty*4+i)*64 + d];
            #pragma unroll
            for (int dd = 0; dd < 4; dd++) {
                float4 t = *(const float4*)&KPs[(d+dd)*64 + tx*4];
                kr[dd][0] = t.x; kr[dd][1] = t.y; kr[dd][2] = t.z; kr[dd][3] = t.w;
            }
            #pragma unroll
            for (int i = 0; i < 4; i++)
                #pragma unroll
                for (int j = 0; j < 4; j++)
                    s[i][j] += q4[i].x*kr[0][j] + q4[i].y*kr[1][j]
                             + q4[i].z*kr[2][j] + q4[i].w*kr[3][j];
        }

        // Scale + causal mask (diagonal tile only)
        const bool diag = causal && (kt == qt);
        float tmax[4];
        #pragma unroll
        for (int i = 0; i < 4; i++) {
            float mm = -1e30f;
            #pragma unroll
            for (int j = 0; j < 4; j++) {
                float sv = s[i][j] * 0.125f;
                if (diag && (tx*4 + j) > (ty*4 + i)) sv = -1e30f;
                s[i][j] = sv;
                mm = fmaxf(mm, sv);
            }
            tmax[i] = mm;
        }
        // Row reductions across the 16 lanes owning this row
        #pragma unroll
        for (int off = 1; off < 16; off <<= 1)
            #pragma unroll
            for (int i = 0; i < 4; i++)
                tmax[i] = fmaxf(tmax[i], __shfl_xor_sync(0xffffffffu, tmax[i], off));

        float mn[4], tsum[4];
        #pragma unroll
        for (int i = 0; i < 4; i++) {
            mn[i] = fmaxf(mrow[i], tmax[i]);
            float ss = 0.f;
            #pragma unroll
            for (int j = 0; j < 4; j++) {
                float p = __expf(s[i][j] - mn[i]);
                s[i][j] = p;
                ss += p;
            }
            tsum[i] = ss;
        }
        #pragma unroll
        for (int off = 1; off < 16; off <<= 1)
            #pragma unroll
            for (int i = 0; i < 4; i++)
                tsum[i] += __shfl_xor_sync(0xffffffffu, tsum[i], off);

        #pragma unroll
        for (int i = 0; i < 4; i++) {
            float alpha = __expf(mrow[i] - mn[i]);
            lrow[i] = lrow[i]*alpha + tsum[i];
            mrow[i] = mn[i];
            #pragma unroll
            for (int j = 0; j < 4; j++) accO[i][j] *= alpha;
        }

        __syncthreads();  // everyone done reading KPs as K^T
        #pragma unroll
        for (int i = 0; i < 4; i++) {
            float4 p4 = make_float4(s[i][0], s[i][1], s[i][2], s[i][3]);
            *(float4*)&KPs[(ty*4+i)*64 + tx*4] = p4;
        }
        __syncthreads();  // P visible

        // accO += P @ V (V already pad-folded)
        #pragma unroll
        for (int k = 0; k < 64; k += 4) {
            float4 p4[4];
            float vr[4][4];
            #pragma unroll
            for (int i = 0; i < 4; i++)
                p4[i] = *(const float4*)&KPs[(ty*4+i)*64 + k];
            #pragma unroll
            for (int dd = 0; dd < 4; dd++) {
                float4 t = *(const float4*)&Vs[(k+dd)*64 + tx*4];
                vr[dd][0] = t.x; vr[dd][1] = t.y; vr[dd][2] = t.z; vr[dd][3] = t.w;
            }
            #pragma unroll
            for (int i = 0; i < 4; i++)
                #pragma unroll
                for (int j = 0; j < 4; j++)
                    accO[i][j] += p4[i].x*vr[0][j] + p4[i].y*vr[1][j]
                                + p4[i].z*vr[2][j] + p4[i].w*vr[3][j];
        }
    }

    // Finalize: divide by l, apply pad[q], write [B,S,D] layout
    #pragma unroll
    for (int i = 0; i < 4; i++) {
        int q = q0 + ty*4 + i;
        float pq = pad[b*NS + q] ? 1.f : 0.f;
        float inv = pq / lrow[i];
        float4 o;
        o.x = accO[i][0]*inv; o.y = accO[i][1]*inv;
        o.z = accO[i][2]*inv; o.w = accO[i][3]*inv;
        *(float4*)&g_ctx[((size_t)b*NS + q)*ND + h*64 + tx*4] = o;
    }
}

// ---------------------------------------------------------------------------
extern "C" void kernel_launch(void* const* d_in, const int* in_sizes, int n_in,
                              void* d_out, int out_size)
{
    const float* x    = (const float*)d_in[0];
    const int*   pad  = (const int*)d_in[1];
    const float* Wqkv = (const float*)d_in[2];
    const float* bqkv = (const float*)d_in[3];
    const float* Wo   = (const float*)d_in[4];
    const float* bo   = (const float*)d_in[5];
    const int*   am   = (n_in > 6) ? (const int*)d_in[6] : nullptr;

    float* ctx_ptr = nullptr;
    cudaGetSymbolAddress((void**)&ctx_ptr, g_ctx);

    // 1) QKV projection with scatter epilogue
    dim3 g1(3*ND/128, (NB*NS)/128);   // (24, 64)
    sgemm_nt<ND, 0, 3*ND><<<g1, 256>>>(x, Wqkv, bqkv, nullptr);

    // 2) Flash attention
    dim3 g2(NS/64, NB*NH);            // (32, 64)
    flash_attn<<<g2, 256>>>(pad, am);

    // 3) Output projection
    dim3 g3(ND/128, (NB*NS)/128);     // (8, 64)
    sgemm_nt<ND, 1, ND><<<g3, 256>>>(ctx_ptr, Wo, bo, (float*)d_out);
}

// round 2
// speedup vs baseline: 3.7023x; 3.7023x over previous
#include <cuda_runtime.h>
#include <cstdint>

#define NB 4
#define NS 2048
#define ND 1024
#define NH 16
#define NHD 64

// Scratch (device globals — allocation-free rule)
__device__ float g_Q[NB*NH*NS*NHD];
__device__ float g_K[NB*NH*NS*NHD];
__device__ float g_V[NB*NH*NS*NHD];
__device__ float g_ctx[NB*NS*ND];
__device__ float g_xr[NB*NS*ND];        // tf32-rounded x
__device__ float g_wqkvr[3*ND*ND];      // tf32-rounded Wqkv
__device__ float g_wor[ND*ND];          // tf32-rounded Wo

// ---------------------------------------------------------------------------
// helpers
// ---------------------------------------------------------------------------
__device__ __forceinline__ float tf32r(float f) {
    uint32_t u;
    asm("cvt.rna.tf32.f32 %0, %1;" : "=r"(u) : "f"(f));
    return __uint_as_float(u);
}

__device__ __forceinline__ void mma8(float4& d,
                                     uint32_t a0, uint32_t a1, uint32_t a2, uint32_t a3,
                                     uint32_t b0, uint32_t b1) {
    asm volatile("mma.sync.aligned.m16n8k8.row.col.f32.tf32.tf32.f32 "
                 "{%0,%1,%2,%3}, {%4,%5,%6,%7}, {%8,%9}, {%0,%1,%2,%3};"
                 : "+f"(d.x), "+f"(d.y), "+f"(d.z), "+f"(d.w)
                 : "r"(a0), "r"(a1), "r"(a2), "r"(a3), "r"(b0), "r"(b1));
}

__device__ __forceinline__ void cp16(float* s, const float* g) {
    uint32_t sa = (uint32_t)__cvta_generic_to_shared(s);
    asm volatile("cp.async.cg.shared.global [%0], [%1], 16;" :: "r"(sa), "l"(g) : "memory");
}
__device__ __forceinline__ void cp_commit() { asm volatile("cp.async.commit_group;" ::: "memory"); }
__device__ __forceinline__ void cp_wait2()  { asm volatile("cp.async.wait_group 2;" ::: "memory"); }

// ---------------------------------------------------------------------------
// tf32 rounding prepass
// ---------------------------------------------------------------------------
__global__ void round_tf32_k(const float* __restrict__ in, float* __restrict__ out, int n4) {
    int i = blockIdx.x * blockDim.x + threadIdx.x;
    if (i < n4) {
        float4 v = ((const float4*)in)[i];
        v.x = tf32r(v.x); v.y = tf32r(v.y); v.z = tf32r(v.z); v.w = tf32r(v.w);
        ((float4*)out)[i] = v;
    }
}

// ---------------------------------------------------------------------------
// tf32 mma GEMM (NT): C[M,N] = A[M,1024] @ W[N,1024]^T + bias
// BM=BN=128, BK=32, 256 thr (8 warps 4x2), 3-stage cp.async, XOR-swizzled smem.
// EPI==0: scatter into g_Q/g_K/g_V (tf32-rounded). EPI==1: plain store + bias.
// Inputs must be tf32-pre-rounded.
// ---------------------------------------------------------------------------
template<int EPI, int NDIM>
__global__ void __launch_bounds__(256, 2)
mma_gemm(const float* __restrict__ A, const float* __restrict__ W,
         const float* __restrict__ bias, float* __restrict__ C)
{
    extern __shared__ float sm[];   // 3 stages * (4096 A + 4096 B)

    const int tid = threadIdx.x;
    const int m0 = blockIdx.y * 128;
    const int n0 = blockIdx.x * 128;
    const int warp = tid >> 5;
    const int lane = tid & 31;
    const int wm = warp >> 1;     // 0..3 -> 32 rows each
    const int wn = warp & 1;      // 0..1 -> 64 cols each
    const int g = lane >> 2;      // 0..7
    const int t = lane & 3;       // 0..3

    float4 acc[2][8];
    #pragma unroll
    for (int i = 0; i < 2; i++)
        #pragma unroll
        for (int j = 0; j < 8; j++) acc[i][j] = make_float4(0.f,0.f,0.f,0.f);

    auto issue = [&](int buf, int k0) {
        float* dA = sm + buf * 8192;
        float* dB = dA + 4096;
        #pragma unroll
        for (int it = 0; it < 4; it++) {
            int fidx = tid + 256 * it;           // 0..1023
            int row = fidx >> 3;                  // 0..127
            int c4 = fidx & 7;                    // 0..7
            int sw = row * 32 + ((c4 * 4) ^ ((row & 7) << 2));
            cp16(dA + sw, A + (size_t)(m0 + row) * 1024 + k0 + c4 * 4);
            cp16(dB + sw, W + (size_t)(n0 + row) * 1024 + k0 + c4 * 4);
        }
    };

    const int NT = 1024 / 32;     // 32 k-stages
    issue(0, 0);  cp_commit();
    issue(1, 32); cp_commit();

    for (int s = 0; s < NT; s++) {
        if (s + 2 < NT) issue((s + 2) % 3, (s + 2) * 32);
        cp_commit();
        cp_wait2();
        __syncthreads();

        const float* As = sm + (s % 3) * 8192;
        const float* Bs = As + 4096;

        #pragma unroll
        for (int ks = 0; ks < 4; ks++) {
            const int kb = ks * 8;
            const int x0 = (kb + t) ^ (g << 2);
            const int x1 = (kb + t + 4) ^ (g << 2);
            uint32_t af[2][4];
            #pragma unroll
            for (int i = 0; i < 2; i++) {
                int r = wm * 32 + 16 * i + g;
                af[i][0] = __float_as_uint(As[r * 32 + x0]);
                af[i][1] = __float_as_uint(As[(r + 8) * 32 + x0]);
                af[i][2] = __float_as_uint(As[r * 32 + x1]);
                af[i][3] = __float_as_uint(As[(r + 8) * 32 + x1]);
            }
            #pragma unroll
            for (int j = 0; j < 8; j++) {
                int n = wn * 64 + 8 * j + g;
                uint32_t b0 = __float_as_uint(Bs[n * 32 + x0]);
                uint32_t b1 = __float_as_uint(Bs[n * 32 + x1]);
                #pragma unroll
                for (int i = 0; i < 2; i++)
                    mma8(acc[i][j], af[i][0], af[i][1], af[i][2], af[i][3], b0, b1);
            }
        }
        __syncthreads();
    }

    if (EPI == 0) {
        // scatter into Q/K/V: n -> head = n/192, r = n%192
        #pragma unroll
        for (int i = 0; i < 2; i++) {
            int r0 = m0 + wm * 32 + 16 * i + g;
            int r1 = r0 + 8;
            #pragma unroll
            for (int j = 0; j < 8; j++) {
                int c0 = n0 + wn * 64 + 8 * j + 2 * t;
                float vals[4] = {acc[i][j].x, acc[i][j].y, acc[i][j].z, acc[i][j].w};
                int   ms[4]   = {r0, r0, r1, r1};
                int   ns[4]   = {c0, c0 + 1, c0, c0 + 1};
                #pragma unroll
                for (int e = 0; e < 4; e++) {
                    int n = ns[e], m = ms[e];
                    float v = tf32r(vals[e] + bias[n]);
                    int head = n / 192;
                    int rr = n - head * 192;
                    int b = m >> 11;
                    int ss = m & (NS - 1);
                    size_t base = ((size_t)(b * NH + head) * NS + ss) * NHD;
                    if (rr < 64)       g_Q[base + rr]       = v;
                    else if (rr < 128) g_K[base + rr - 64]  = v;
                    else               g_V[base + rr - 128] = v;
                }
            }
        }
    } else {
        #pragma unroll
        for (int i = 0; i < 2; i++) {
            int r0 = m0 + wm * 32 + 16 * i + g;
            int r1 = r0 + 8;
            #pragma unroll
            for (int j = 0; j < 8; j++) {
                int c0 = n0 + wn * 64 + 8 * j + 2 * t;
                float b0 = bias[c0], b1 = bias[c0 + 1];
                float2 o0 = make_float2(acc[i][j].x + b0, acc[i][j].y + b1);
                float2 o1 = make_float2(acc[i][j].z + b0, acc[i][j].w + b1);
                *(float2*)&C[(size_t)r0 * NDIM + c0] = o0;
                *(float2*)&C[(size_t)r1 * NDIM + c0] = o1;
            }
        }
    }
}

// ---------------------------------------------------------------------------
// Flash attention with tf32 mma. 128 threads (4 warps), 64x64 tiles.
// Pad semantics match reference: denominator unpadded; pad[k] folded into V;
// pad[q] applied at output. P reuses K smem buffer.
// ---------------------------------------------------------------------------
__global__ void __launch_bounds__(128, 4)
flash_mma(const int* __restrict__ pad, const int* __restrict__ amask)
{
    extern __shared__ float sm[];
    float* Qs  = sm;                 // [64][68]
    float* KPs = sm + 64 * 68;       // [64][68]  (K during S, P during PV)
    float* Vs  = sm + 2 * 64 * 68;   // [64][72]

    const int tid = threadIdx.x;
    const int qt = blockIdx.x;       // 0..31
    const int bh = blockIdx.y;       // 0..63
    const int b  = bh >> 4;
    const int h  = bh & 15;
    const int q0 = qt * 64;
    const int causal = amask ? (amask[0] != 0) : 1;

    const int warp = tid >> 5;
    const int lane = tid & 31;
    const int rbase = warp * 16;
    const int g = lane >> 2;
    const int t = lane & 3;

    // load Q tile [64][64] -> Qs stride 68
    {
        const float* Qg = g_Q + ((size_t)bh * NS + q0) * NHD;
        #pragma unroll
        for (int it = 0; it < 8; it++) {
            int fidx = tid + 128 * it;
            int row = fidx >> 4;
            int c4 = (fidx & 15) * 4;
            *(float4*)&Qs[row * 68 + c4] = *(const float4*)(Qg + row * 64 + c4);
        }
    }

    float m0r = -1e30f, m1r = -1e30f, l0 = 0.f, l1 = 0.f;
    float4 accO[8];
    #pragma unroll
    for (int j = 0; j < 8; j++) accO[j] = make_float4(0.f,0.f,0.f,0.f);

    const int rowa = q0 + rbase + g;
    const int rowb = rowa + 8;
    const int ktmax = causal ? qt : (NS / 64 - 1);

    for (int kt = 0; kt <= ktmax; kt++) {
        const int k0 = kt * 64;
        if (kt) __syncthreads();   // prior PV done with KPs/Vs

        // load K tile -> KPs, V tile (pad-folded) -> Vs
        {
            const float* Kg = g_K + ((size_t)bh * NS + k0) * NHD;
            const float* Vg = g_V + ((size_t)bh * NS + k0) * NHD;
            #pragma unroll
            for (int it = 0; it < 8; it++) {
                int fidx = tid + 128 * it;
                int row = fidx >> 4;
                int c4 = (fidx & 15) * 4;
                *(float4*)&KPs[row * 68 + c4] = *(const float4*)(Kg + row * 64 + c4);
                float pk = pad[b * NS + k0 + row] ? 1.f : 0.f;
                float4 vv = *(const float4*)(Vg + row * 64 + c4);
                vv.x *= pk; vv.y *= pk; vv.z *= pk; vv.w *= pk;
                *(float4*)&Vs[row * 72 + c4] = vv;
            }
        }
        __syncthreads();

        // S = Q @ K^T  (m16 x n64, k=64)
        float4 sfr[8];
        #pragma unroll
        for (int j = 0; j < 8; j++) sfr[j] = make_float4(0.f,0.f,0.f,0.f);
        #pragma unroll
        for (int ks = 0; ks < 8; ks++) {
            const int kb = ks * 8;
            uint32_t a0 = __float_as_uint(Qs[(rbase + g) * 68 + kb + t]);
            uint32_t a1 = __float_as_uint(Qs[(rbase + g + 8) * 68 + kb + t]);
            uint32_t a2 = __float_as_uint(Qs[(rbase + g) * 68 + kb + t + 4]);
            uint32_t a3 = __float_as_uint(Qs[(rbase + g + 8) * 68 + kb + t + 4]);
            #pragma unroll
            for (int j = 0; j < 8; j++) {
                uint32_t b0 = __float_as_uint(KPs[(8 * j + g) * 68 + kb + t]);
                uint32_t b1 = __float_as_uint(KPs[(8 * j + g) * 68 + kb + t + 4]);
                mma8(sfr[j], a0, a1, a2, a3, b0, b1);
            }
        }

        // scale + causal mask + online softmax
        const bool diag = causal && (kt == qt);
        float mx0 = -1e30f, mx1 = -1e30f;
        #pragma unroll
        for (int j = 0; j < 8; j++) {
            int c0 = k0 + 8 * j + 2 * t;
            int c1 = c0 + 1;
            float sx = sfr[j].x * 0.125f;
            float sy = sfr[j].y * 0.125f;
            float sz = sfr[j].z * 0.125f;
            float sw = sfr[j].w * 0.125f;
            if (diag) {
                if (c0 > rowa) sx = -1e30f;
                if (c1 > rowa) sy = -1e30f;
                if (c0 > rowb) sz = -1e30f;
                if (c1 > rowb) sw = -1e30f;
            }
            sfr[j] = make_float4(sx, sy, sz, sw);
            mx0 = fmaxf(mx0, fmaxf(sx, sy));
            mx1 = fmaxf(mx1, fmaxf(sz, sw));
        }
        #pragma unroll
        for (int off = 1; off < 4; off <<= 1) {
            mx0 = fmaxf(mx0, __shfl_xor_sync(0xffffffffu, mx0, off));
            mx1 = fmaxf(mx1, __shfl_xor_sync(0xffffffffu, mx1, off));
        }
        float nm0 = fmaxf(m0r, mx0);
        float nm1 = fmaxf(m1r, mx1);
        float s0 = 0.f, s1 = 0.f;
        #pragma unroll
        for (int j = 0; j < 8; j++) {
            float px = __expf(sfr[j].x - nm0);
            float py = __expf(sfr[j].y - nm0);
            float pz = __expf(sfr[j].z - nm1);
            float pw = __expf(sfr[j].w - nm1);
            sfr[j] = make_float4(px, py, pz, pw);
            s0 += px + py;
            s1 += pz + pw;
        }
        #pragma unroll
        for (int off = 1; off < 4; off <<= 1) {
            s0 += __shfl_xor_sync(0xffffffffu, s0, off);
            s1 += __shfl_xor_sync(0xffffffffu, s1, off);
        }
        float al0 = __expf(m0r - nm0);
        float al1 = __expf(m1r - nm1);
        l0 = l0 * al0 + s0;  m0r = nm0;
        l1 = l1 * al1 + s1;  m1r = nm1;
        #pragma unroll
        for (int j = 0; j < 8; j++) {
            accO[j].x *= al0; accO[j].y *= al0;
            accO[j].z *= al1; accO[j].w *= al1;
        }

        __syncthreads();   // all warps done reading KPs as K
        // write P (tf32-rounded) into KPs
        #pragma unroll
        for (int j = 0; j < 8; j++) {
            float2 p01 = make_float2(tf32r(sfr[j].x), tf32r(sfr[j].y));
            float2 p23 = make_float2(tf32r(sfr[j].z), tf32r(sfr[j].w));
            *(float2*)&KPs[(rbase + g) * 68 + 8 * j + 2 * t] = p01;
            *(float2*)&KPs[(rbase + g + 8) * 68 + 8 * j + 2 * t] = p23;
        }
        __syncthreads();

        // accO += P @ V   (k = kv 64, n = d 64)
        #pragma unroll
        for (int ks = 0; ks < 8; ks++) {
            const int kb = ks * 8;
            uint32_t a0 = __float_as_uint(KPs[(rbase + g) * 68 + kb + t]);
            uint32_t a1 = __float_as_uint(KPs[(rbase + g + 8) * 68 + kb + t]);
            uint32_t a2 = __float_as_uint(KPs[(rbase + g) * 68 + kb + t + 4]);
            uint32_t a3 = __float_as_uint(KPs[(rbase + g + 8) * 68 + kb + t + 4]);
            #pragma unroll
            for (int j = 0; j < 8; j++) {
                uint32_t b0 = __float_as_uint(Vs[(kb + t) * 72 + 8 * j + g]);
                uint32_t b1 = __float_as_uint(Vs[(kb + t + 4) * 72 + 8 * j + g]);
                mma8(accO[j], a0, a1, a2, a3, b0, b1);
            }
        }
    }

    // finalize: /l, pad[q], tf32-round (feeds proj GEMM), store to g_ctx
    float pq0 = pad[b * NS + rowa] ? 1.f : 0.f;
    float pq1 = pad[b * NS + rowb] ? 1.f : 0.f;
    float inv0 = pq0 / l0;
    float inv1 = pq1 / l1;
    #pragma unroll
    for (int j = 0; j < 8; j++) {
        int col = h * 64 + 8 * j + 2 * t;
        float2 o0 = make_float2(tf32r(accO[j].x * inv0), tf32r(accO[j].y * inv0));
        float2 o1 = make_float2(tf32r(accO[j].z * inv1), tf32r(accO[j].w * inv1));
        *(float2*)&g_ctx[((size_t)b * NS + rowa) * ND + col] = o0;
        *(float2*)&g_ctx[((size_t)b * NS + rowb) * ND + col] = o1;
    }
}

// ---------------------------------------------------------------------------
extern "C" void kernel_launch(void* const* d_in, const int* in_sizes, int n_in,
                              void* d_out, int out_size)
{
    const float* x    = (const float*)d_in[0];
    const int*   pad  = (const int*)d_in[1];
    const float* Wqkv = (const float*)d_in[2];
    const float* bqkv = (const float*)d_in[3];
    const float* Wo   = (const float*)d_in[4];
    const float* bo   = (const float*)d_in[5];
    const int*   am   = (n_in > 6) ? (const int*)d_in[6] : nullptr;

    float *xr, *wqkvr, *wor, *ctx;
    cudaGetSymbolAddress((void**)&xr,    g_xr);
    cudaGetSymbolAddress((void**)&wqkvr, g_wqkvr);
    cudaGetSymbolAddress((void**)&wor,   g_wor);
    cudaGetSymbolAddress((void**)&ctx,   g_ctx);

    const int GEMM_SMEM = 3 * 8192 * 4;           // 96 KB
    const int ATT_SMEM  = (64*68*2 + 64*72) * 4;  // 53248 B
    cudaFuncSetAttribute(mma_gemm<0, 3*ND>, cudaFuncAttributeMaxDynamicSharedMemorySize, GEMM_SMEM);
    cudaFuncSetAttribute(mma_gemm<1, ND>,   cudaFuncAttributeMaxDynamicSharedMemorySize, GEMM_SMEM);
    cudaFuncSetAttribute(flash_mma,         cudaFuncAttributeMaxDynamicSharedMemorySize, ATT_SMEM);

    // 0) tf32 rounding prepass
    {
        int n;
        n = NB*NS*ND/4;  round_tf32_k<<<(n+255)/256, 256>>>(x, xr, n);
        n = 3*ND*ND/4;   round_tf32_k<<<(n+255)/256, 256>>>(Wqkv, wqkvr, n);
        n = ND*ND/4;     round_tf32_k<<<(n+255)/256, 256>>>(Wo, wor, n);
    }

    // 1) QKV projection + scatter
    dim3 g1(3*ND/128, (NB*NS)/128);   // (24, 64)
    mma_gemm<0, 3*ND><<<g1, 256, GEMM_SMEM>>>(xr, wqkvr, bqkv, nullptr);

    // 2) flash attention
    dim3 g2(NS/64, NB*NH);            // (32, 64)
    flash_mma<<<g2, 128, ATT_SMEM>>>(pad, am);

    // 3) output projection
    dim3 g3(ND/128, (NB*NS)/128);     // (8, 64)
    mma_gemm<1, ND><<<g3, 256, GEMM_SMEM>>>(ctx, wor, bo, (float*)d_out);
}

// round 4
// speedup vs baseline: 7.1167x; 1.9222x over previous
#include <cuda_runtime.h>
#include <cuda_fp16.h>
#include <cstdint>

#define NB 4
#define NS 2048
#define ND 1024
#define NH 16
#define NHD 64

// Scratch (device globals — allocation-free rule)
__device__ __half g_Q[NB*NH*NS*NHD];
__device__ __half g_K[NB*NH*NS*NHD];
__device__ __half g_V[NB*NH*NS*NHD];     // pad[k] pre-folded
__device__ __half g_ctx[NB*NS*ND];
__device__ __half g_xh[NB*NS*ND];
__device__ __half g_wqkvh[3*ND*ND];
__device__ __half g_woh[ND*ND];

// ---------------------------------------------------------------------------
// helpers
// ---------------------------------------------------------------------------
__device__ __forceinline__ void mma16(float4& d,
                                      uint32_t a0, uint32_t a1, uint32_t a2, uint32_t a3,
                                      uint32_t b0, uint32_t b1) {
    asm volatile("mma.sync.aligned.m16n8k16.row.col.f32.f16.f16.f32 "
                 "{%0,%1,%2,%3}, {%4,%5,%6,%7}, {%8,%9}, {%0,%1,%2,%3};"
                 : "+f"(d.x), "+f"(d.y), "+f"(d.z), "+f"(d.w)
                 : "r"(a0), "r"(a1), "r"(a2), "r"(a3), "r"(b0), "r"(b1));
}

__device__ __forceinline__ void ldm_x4(uint32_t& r0, uint32_t& r1, uint32_t& r2, uint32_t& r3,
                                       uint32_t addr) {
    asm volatile("ldmatrix.sync.aligned.m8n8.x4.shared.b16 {%0,%1,%2,%3}, [%4];"
                 : "=r"(r0), "=r"(r1), "=r"(r2), "=r"(r3) : "r"(addr));
}

__device__ __forceinline__ void ldm_x4t(uint32_t& r0, uint32_t& r1, uint32_t& r2, uint32_t& r3,
                                        uint32_t addr) {
    asm volatile("ldmatrix.sync.aligned.m8n8.x4.trans.shared.b16 {%0,%1,%2,%3}, [%4];"
                 : "=r"(r0), "=r"(r1), "=r"(r2), "=r"(r3) : "r"(addr));
}

__device__ __forceinline__ void cp16(void* s, const void* g) {
    uint32_t sa = (uint32_t)__cvta_generic_to_shared(s);
    asm volatile("cp.async.cg.shared.global [%0], [%1], 16;" :: "r"(sa), "l"(g) : "memory");
}
__device__ __forceinline__ void cp_commit() { asm volatile("cp.async.commit_group;" ::: "memory"); }
__device__ __forceinline__ void cp_wait2()  { asm volatile("cp.async.wait_group 2;" ::: "memory"); }

// ---------------------------------------------------------------------------
// fp32 -> fp16 prepass
// ---------------------------------------------------------------------------
__global__ void f2h_k(const float* __restrict__ in, __half* __restrict__ out, int n4) {
    int i = blockIdx.x * blockDim.x + threadIdx.x;
    if (i < n4) {
        float4 v = ((const float4*)in)[i];
        __half2 h0 = __floats2half2_rn(v.x, v.y);
        __half2 h1 = __floats2half2_rn(v.z, v.w);
        ((__half2*)out)[i*2]   = h0;
        ((__half2*)out)[i*2+1] = h1;
    }
}

// ---------------------------------------------------------------------------
// fp16 mma GEMM (NT): C[M,N] = A[M,1024] @ W[N,1024]^T + bias
// BM=BN=128, BK=64 halves (128B SW128 rows), 256 thr (8 warps 4x2),
// 3-stage cp.async, ldmatrix fragments.
// EPI==0: half2 scatter into g_Q/g_K/g_V (V pad-folded). EPI==1: fp32 store.
// ---------------------------------------------------------------------------
template<int EPI, int NDIM>
__global__ void __launch_bounds__(256, 2)
hgemm(const __half* __restrict__ A, const __half* __restrict__ W,
      const float* __restrict__ bias, float* __restrict__ C,
      const int* __restrict__ pad)
{
    extern __shared__ char smem[];
    const uint32_t sb = (uint32_t)__cvta_generic_to_shared(smem);

    const int tid  = threadIdx.x;
    const int warp = tid >> 5;
    const int lane = tid & 31;
    const int m0 = blockIdx.y * 128;
    const int n0 = blockIdx.x * 128;
    const int wm = warp >> 1;       // 0..3 -> 32 rows
    const int wn = warp & 1;        // 0..1 -> 64 cols
    const int g = lane >> 2;
    const int t = lane & 3;

    float4 acc[2][8];
    #pragma unroll
    for (int i = 0; i < 2; i++)
        #pragma unroll
        for (int j = 0; j < 8; j++) acc[i][j] = make_float4(0.f,0.f,0.f,0.f);

    auto issue = [&](int buf, int k0) {     // k0 in halves
        char* base = smem + buf * 32768;
        #pragma unroll
        for (int it = 0; it < 4; it++) {
            int cid = tid + 256 * it;       // 0..1023
            int row = cid >> 3;             // 0..127
            int c   = cid & 7;              // 16B chunk in 128B row
            int sw  = row * 128 + ((c ^ (row & 7)) << 4);
            cp16(base + sw,         A + (size_t)(m0 + row) * 1024 + k0 + c * 8);
            cp16(base + 16384 + sw, W + (size_t)(n0 + row) * 1024 + k0 + c * 8);
        }
    };

    const int NT = 1024 / 64;   // 16 stages
    issue(0, 0);  cp_commit();
    issue(1, 64); cp_commit();

    for (int s = 0; s < NT; s++) {
        if (s + 2 < NT) issue((s + 2) % 3, (s + 2) * 64);
        cp_commit();
        cp_wait2();
        __syncthreads();

        const uint32_t As = sb + (s % 3) * 32768;
        const uint32_t Bs = As + 16384;

        #pragma unroll
        for (int ks = 0; ks < 4; ks++) {    // k16 steps
            const int ch = ks * 2 + (lane >> 4);
            uint32_t af[2][4];
            #pragma unroll
            for (int i = 0; i < 2; i++) {
                int row = wm * 32 + i * 16 + (lane & 15);
                ldm_x4(af[i][0], af[i][1], af[i][2], af[i][3],
                       As + row * 128 + ((ch ^ (row & 7)) << 4));
            }
            uint32_t bf[8][2];
            #pragma unroll
            for (int jj = 0; jj < 4; jj++) {
                int row = wn * 64 + jj * 16 + (lane & 15);
                uint32_t r0, r1, r2, r3;
                ldm_x4(r0, r1, r2, r3, Bs + row * 128 + ((ch ^ (row & 7)) << 4));
                bf[2*jj][0]   = r0; bf[2*jj][1]   = r2;
                bf[2*jj+1][0] = r1; bf[2*jj+1][1] = r3;
            }
            #pragma unroll
            for (int i = 0; i < 2; i++)
                #pragma unroll
                for (int j = 0; j < 8; j++)
                    mma16(acc[i][j], af[i][0], af[i][1], af[i][2], af[i][3],
                          bf[j][0], bf[j][1]);
        }
        __syncthreads();
    }

    if (EPI == 0) {
        #pragma unroll
        for (int i = 0; i < 2; i++) {
            #pragma unroll
            for (int rh = 0; rh < 2; rh++) {
                int m = m0 + wm * 32 + 16 * i + g + rh * 8;
                int b_ = m >> 11;
                int s_ = m & (NS - 1);
                float pv = pad[b_ * NS + s_] ? 1.f : 0.f;
                #pragma unroll
                for (int j = 0; j < 8; j++) {
                    int c0 = n0 + wn * 64 + 8 * j + 2 * t;
                    float v0 = (rh ? acc[i][j].z : acc[i][j].x) + bias[c0];
                    float v1 = (rh ? acc[i][j].w : acc[i][j].y) + bias[c0 + 1];
                    int head = c0 / 192;
                    int rr = c0 - head * 192;
                    size_t base = ((size_t)(b_ * NH + head) * NS + s_) * NHD;
                    if (rr < 64)
                        *(__half2*)&g_Q[base + rr] = __floats2half2_rn(v0, v1);
                    else if (rr < 128)
                        *(__half2*)&g_K[base + rr - 64] = __floats2half2_rn(v0, v1);
                    else
                        *(__half2*)&g_V[base + rr - 128] = __floats2half2_rn(v0 * pv, v1 * pv);
                }
            }
        }
    } else {
        #pragma unroll
        for (int i = 0; i < 2; i++) {
            int r0 = m0 + wm * 32 + 16 * i + g;
            int r1 = r0 + 8;
            #pragma unroll
            for (int j = 0; j < 8; j++) {
                int c0 = n0 + wn * 64 + 8 * j + 2 * t;
                float b0v = bias[c0], b1v = bias[c0 + 1];
                *(float2*)&C[(size_t)r0 * NDIM + c0] =
                    make_float2(acc[i][j].x + b0v, acc[i][j].y + b1v);
                *(float2*)&C[(size_t)r1 * NDIM + c0] =
                    make_float2(acc[i][j].z + b0v, acc[i][j].w + b1v);
            }
        }
    }
}

// ---------------------------------------------------------------------------
// Flash attention, fp16 mma + ldmatrix. 128 threads, 64x64 tiles, SW128 smem.
// V already pad-folded. Denominator unpadded; pad[q] at output.
// ---------------------------------------------------------------------------
__global__ void __launch_bounds__(128, 4)
flash_h(const int* __restrict__ pad, const int* __restrict__ amask)
{
    __shared__ char smem[3 * 8192];
    const uint32_t sb = (uint32_t)__cvta_generic_to_shared(smem);
    const uint32_t Qb = sb, KPb = sb + 8192, Vb = sb + 16384;

    const int tid = threadIdx.x;
    const int qt = blockIdx.x;
    const int bh = blockIdx.y;
    const int b  = bh >> 4;
    const int h  = bh & 15;
    const int q0 = qt * 64;
    const int causal = amask ? (amask[0] != 0) : 1;

    const int warp = tid >> 5;
    const int lane = tid & 31;
    const int rbase = warp * 16;
    const int g = lane >> 2;
    const int t = lane & 3;

    // load Q tile [64][64] half, SW128 swizzle
    {
        const __half* Qg = g_Q + ((size_t)bh * NS + q0) * NHD;
        #pragma unroll
        for (int it = 0; it < 4; it++) {
            int cid = tid + 128 * it;       // 0..511
            int row = cid >> 3;
            int c   = cid & 7;
            int off = row * 128 + ((c ^ (row & 7)) << 4);
            *(float4*)(smem + off) = *(const float4*)(Qg + row * 64 + c * 8);
        }
    }

    float m0r = -1e30f, m1r = -1e30f, l0 = 0.f, l1 = 0.f;
    float4 accO[8];
    #pragma unroll
    for (int j = 0; j < 8; j++) accO[j] = make_float4(0.f,0.f,0.f,0.f);

    const int rowa = q0 + rbase + g;
    const int rowb = rowa + 8;
    const int ktmax = causal ? qt : (NS / 64 - 1);

    for (int kt = 0; kt <= ktmax; kt++) {
        const int k0 = kt * 64;
        if (kt) __syncthreads();   // prior PV done with KPb/Vb

        {
            const __half* Kg = g_K + ((size_t)bh * NS + k0) * NHD;
            const __half* Vg = g_V + ((size_t)bh * NS + k0) * NHD;
            #pragma unroll
            for (int it = 0; it < 4; it++) {
                int cid = tid + 128 * it;
                int row = cid >> 3;
                int c   = cid & 7;
                int off = row * 128 + ((c ^ (row & 7)) << 4);
                *(float4*)(smem + 8192 + off)  = *(const float4*)(Kg + row * 64 + c * 8);
                *(float4*)(smem + 16384 + off) = *(const float4*)(Vg + row * 64 + c * 8);
            }
        }
        __syncthreads();

        // S = Q @ K^T
        float4 sfr[8];
        #pragma unroll
        for (int j = 0; j < 8; j++) sfr[j] = make_float4(0.f,0.f,0.f,0.f);
        #pragma unroll
        for (int ks = 0; ks < 4; ks++) {
            const int ch = ks * 2 + (lane >> 4);
            uint32_t a0, a1, a2, a3;
            {
                int row = rbase + (lane & 15);
                ldm_x4(a0, a1, a2, a3, Qb + row * 128 + ((ch ^ (row & 7)) << 4));
            }
            #pragma unroll
            for (int jj = 0; jj < 4; jj++) {
                int row = jj * 16 + (lane & 15);
                uint32_t r0, r1, r2, r3;
                ldm_x4(r0, r1, r2, r3, KPb + row * 128 + ((ch ^ (row & 7)) << 4));
                mma16(sfr[2*jj],   a0, a1, a2, a3, r0, r2);
                mma16(sfr[2*jj+1], a0, a1, a2, a3, r1, r3);
            }
        }

        // scale + causal + online softmax (fp32)
        const bool diag = causal && (kt == qt);
        float mx0 = -1e30f, mx1 = -1e30f;
        #pragma unroll
        for (int j = 0; j < 8; j++) {
            int c0 = k0 + 8 * j + 2 * t;
            int c1 = c0 + 1;
            float sx = sfr[j].x * 0.125f;
            float sy = sfr[j].y * 0.125f;
            float sz = sfr[j].z * 0.125f;
            float sw = sfr[j].w * 0.125f;
            if (diag) {
                if (c0 > rowa) sx = -1e30f;
                if (c1 > rowa) sy = -1e30f;
                if (c0 > rowb) sz = -1e30f;
                if (c1 > rowb) sw = -1e30f;
            }
            sfr[j] = make_float4(sx, sy, sz, sw);
            mx0 = fmaxf(mx0, fmaxf(sx, sy));
            mx1 = fmaxf(mx1, fmaxf(sz, sw));
        }
        #pragma unroll
        for (int off = 1; off < 4; off <<= 1) {
            mx0 = fmaxf(mx0, __shfl_xor_sync(0xffffffffu, mx0, off));
            mx1 = fmaxf(mx1, __shfl_xor_sync(0xffffffffu, mx1, off));
        }
        float nm0 = fmaxf(m0r, mx0);
        float nm1 = fmaxf(m1r, mx1);
        float s0 = 0.f, s1 = 0.f;
        #pragma unroll
        for (int j = 0; j < 8; j++) {
            float px = __expf(sfr[j].x - nm0);
            float py = __expf(sfr[j].y - nm0);
            float pz = __expf(sfr[j].z - nm1);
            float pw = __expf(sfr[j].w - nm1);
            sfr[j] = make_float4(px, py, pz, pw);
            s0 += px + py;
            s1 += pz + pw;
        }
        #pragma unroll
        for (int off = 1; off < 4; off <<= 1) {
            s0 += __shfl_xor_sync(0xffffffffu, s0, off);
            s1 += __shfl_xor_sync(0xffffffffu, s1, off);
        }
        float al0 = __expf(m0r - nm0);
        float al1 = __expf(m1r - nm1);
        l0 = l0 * al0 + s0;  m0r = nm0;
        l1 = l1 * al1 + s1;  m1r = nm1;
        #pragma unroll
        for (int j = 0; j < 8; j++) {
            accO[j].x *= al0; accO[j].y *= al0;
            accO[j].z *= al1; accO[j].w *= al1;
        }

        __syncthreads();   // all warps done reading K from KPb
        // write P (half) into KPb with same swizzle
        #pragma unroll
        for (int j = 0; j < 8; j++) {
            int col = 8 * j + 2 * t;
            int ra = rbase + g, rb = ra + 8;
            int offa = ra * 128 + ((j ^ (ra & 7)) << 4) + (col & 7) * 2;
            int offb = rb * 128 + ((j ^ (rb & 7)) << 4) + (col & 7) * 2;
            *(__half2*)(smem + 8192 + offa) = __floats2half2_rn(sfr[j].x, sfr[j].y);
            *(__half2*)(smem + 8192 + offb) = __floats2half2_rn(sfr[j].z, sfr[j].w);
        }
        __syncthreads();

        // accO += P @ V (B = V^T via ldmatrix.trans)
        #pragma unroll
        for (int ks = 0; ks < 4; ks++) {
            uint32_t a0, a1, a2, a3;
            {
                int row = rbase + (lane & 15);
                int ch = ks * 2 + (lane >> 4);
                ldm_x4(a0, a1, a2, a3, KPb + row * 128 + ((ch ^ (row & 7)) << 4));
            }
            #pragma unroll
            for (int jj = 0; jj < 4; jj++) {
                int kvrow = ks * 16 + (lane & 15);
                int dch = jj * 2 + (lane >> 4);
                uint32_t r0, r1, r2, r3;
                ldm_x4t(r0, r1, r2, r3, Vb + kvrow * 128 + ((dch ^ (kvrow & 7)) << 4));
                mma16(accO[2*jj],   a0, a1, a2, a3, r0, r1);
                mma16(accO[2*jj+1], a0, a1, a2, a3, r2, r3);
            }
        }
    }

    // finalize: /l, pad[q], store half ctx
    float pq0 = pad[b * NS + rowa] ? 1.f : 0.f;
    float pq1 = pad[b * NS + rowb] ? 1.f : 0.f;
    float inv0 = pq0 / l0;
    float inv1 = pq1 / l1;
    #pragma unroll
    for (int j = 0; j < 8; j++) {
        int col = h * 64 + 8 * j + 2 * t;
        *(__half2*)&g_ctx[((size_t)b * NS + rowa) * ND + col] =
            __floats2half2_rn(accO[j].x * inv0, accO[j].y * inv0);
        *(__half2*)&g_ctx[((size_t)b * NS + rowb) * ND + col] =
            __floats2half2_rn(accO[j].z * inv1, accO[j].w * inv1);
    }
}

// ---------------------------------------------------------------------------
extern "C" void kernel_launch(void* const* d_in, const int* in_sizes, int n_in,
                              void* d_out, int out_size)
{
    const float* x    = (const float*)d_in[0];
    const int*   pad  = (const int*)d_in[1];
    const float* Wqkv = (const float*)d_in[2];
    const float* bqkv = (const float*)d_in[3];
    const float* Wo   = (const float*)d_in[4];
    const float* bo   = (const float*)d_in[5];
    const int*   am   = (n_in > 6) ? (const int*)d_in[6] : nullptr;

    __half *xh, *wqkvh, *woh, *ctx;
    cudaGetSymbolAddress((void**)&xh,    g_xh);
    cudaGetSymbolAddress((void**)&wqkvh, g_wqkvh);
    cudaGetSymbolAddress((void**)&woh,   g_woh);
    cudaGetSymbolAddress((void**)&ctx,   g_ctx);

    const int GEMM_SMEM = 3 * 32768;   // 96 KB
    cudaFuncSetAttribute(hgemm<0, 3*ND>, cudaFuncAttributeMaxDynamicSharedMemorySize, GEMM_SMEM);
    cudaFuncSetAttribute(hgemm<1, ND>,   cudaFuncAttributeMaxDynamicSharedMemorySize, GEMM_SMEM);

    // 0) fp16 conversion prepass
    {
        int n;
        n = NB*NS*ND/4;  f2h_k<<<(n+255)/256, 256>>>(x, xh, n);
        n = 3*ND*ND/4;   f2h_k<<<(n+255)/256, 256>>>(Wqkv, wqkvh, n);
        n = ND*ND/4;     f2h_k<<<(n+255)/256, 256>>>(Wo, woh, n);
    }

    // 1) QKV projection + scatter (V pad-folded)
    dim3 g1(3*ND/128, (NB*NS)/128);   // (24, 64)
    hgemm<0, 3*ND><<<g1, 256, GEMM_SMEM>>>(xh, wqkvh, bqkv, nullptr, pad);

    // 2) flash attention
    dim3 g2(NS/64, NB*NH);            // (32, 64)
    flash_h<<<g2, 128>>>(pad, am);

    // 3) output projection
    dim3 g3(ND/128, (NB*NS)/128);     // (8, 64)
    hgemm<1, ND><<<g3, 256, GEMM_SMEM>>>(ctx, woh, bo, (float*)d_out, nullptr);
}

// round 5
// speedup vs baseline: 7.5746x; 1.0643x over previous
#include <cuda_runtime.h>
#include <cuda_fp16.h>
#include <cstdint>

#define NB 4
#define NS 2048
#define ND 1024
#define NH 16
#define NHD 64

// Scratch (device globals — allocation-free rule)
__device__ __half g_Q[NB*NH*NS*NHD];     // pre-scaled by 0.125*log2(e)
__device__ __half g_K[NB*NH*NS*NHD];
__device__ __half g_V[NB*NH*NS*NHD];     // pad[k] pre-folded
__device__ __half g_ctx[NB*NS*ND];
__device__ __half g_xh[NB*NS*ND];
__device__ __half g_wqkvh[3*ND*ND];
__device__ __half g_woh[ND*ND];

#define QSCALE 0.1803368801111137f   // 0.125 * log2(e)

// ---------------------------------------------------------------------------
// helpers
// ---------------------------------------------------------------------------
__device__ __forceinline__ void mma16(float4& d,
                                      uint32_t a0, uint32_t a1, uint32_t a2, uint32_t a3,
                                      uint32_t b0, uint32_t b1) {
    asm volatile("mma.sync.aligned.m16n8k16.row.col.f32.f16.f16.f32 "
                 "{%0,%1,%2,%3}, {%4,%5,%6,%7}, {%8,%9}, {%0,%1,%2,%3};"
                 : "+f"(d.x), "+f"(d.y), "+f"(d.z), "+f"(d.w)
                 : "r"(a0), "r"(a1), "r"(a2), "r"(a3), "r"(b0), "r"(b1));
}

__device__ __forceinline__ void ldm_x4(uint32_t& r0, uint32_t& r1, uint32_t& r2, uint32_t& r3,
                                       uint32_t addr) {
    asm volatile("ldmatrix.sync.aligned.m8n8.x4.shared.b16 {%0,%1,%2,%3}, [%4];"
                 : "=r"(r0), "=r"(r1), "=r"(r2), "=r"(r3) : "r"(addr));
}

__device__ __forceinline__ void ldm_x4t(uint32_t& r0, uint32_t& r1, uint32_t& r2, uint32_t& r3,
                                        uint32_t addr) {
    asm volatile("ldmatrix.sync.aligned.m8n8.x4.trans.shared.b16 {%0,%1,%2,%3}, [%4];"
                 : "=r"(r0), "=r"(r1), "=r"(r2), "=r"(r3) : "r"(addr));
}

__device__ __forceinline__ void cp16(void* s, const void* g) {
    uint32_t sa = (uint32_t)__cvta_generic_to_shared(s);
    asm volatile("cp.async.cg.shared.global [%0], [%1], 16;" :: "r"(sa), "l"(g) : "memory");
}
__device__ __forceinline__ void cp_commit() { asm volatile("cp.async.commit_group;" ::: "memory"); }
__device__ __forceinline__ void cp_wait2()  { asm volatile("cp.async.wait_group 2;" ::: "memory"); }

__device__ __forceinline__ float ex2f(float x) {
    float y;
    asm("ex2.approx.ftz.f32 %0, %1;" : "=f"(y) : "f"(x));
    return y;
}

__device__ __forceinline__ uint32_t h2u(float a, float b) {
    __half2 h = __floats2half2_rn(a, b);
    return *(uint32_t*)&h;
}

// ---------------------------------------------------------------------------
// fp32 -> fp16 prepass
// ---------------------------------------------------------------------------
__global__ void f2h_k(const float* __restrict__ in, __half* __restrict__ out, int n4) {
    int i = blockIdx.x * blockDim.x + threadIdx.x;
    if (i < n4) {
        float4 v = ((const float4*)in)[i];
        ((__half2*)out)[i*2]   = __floats2half2_rn(v.x, v.y);
        ((__half2*)out)[i*2+1] = __floats2half2_rn(v.z, v.w);
    }
}

// ---------------------------------------------------------------------------
// fp16 mma GEMM (NT): C[M,N] = A[M,1024] @ W[N,1024]^T + bias
// BM=BN=128, BK=64 halves, 256 thr, 3-stage cp.async, ldmatrix fragments.
// EPI==0: scatter (Q pre-scaled, V pad-folded). EPI==1: fp32 store.
// ---------------------------------------------------------------------------
template<int EPI, int NDIM>
__global__ void __launch_bounds__(256, 2)
hgemm(const __half* __restrict__ A, const __half* __restrict__ W,
      const float* __restrict__ bias, float* __restrict__ C,
      const int* __restrict__ pad)
{
    extern __shared__ char smem[];
    const uint32_t sb = (uint32_t)__cvta_generic_to_shared(smem);

    const int tid  = threadIdx.x;
    const int warp = tid >> 5;
    const int lane = tid & 31;
    const int m0 = blockIdx.y * 128;
    const int n0 = blockIdx.x * 128;
    const int wm = warp >> 1;
    const int wn = warp & 1;
    const int g = lane >> 2;
    const int t = lane & 3;

    float4 acc[2][8];
    #pragma unroll
    for (int i = 0; i < 2; i++)
        #pragma unroll
        for (int j = 0; j < 8; j++) acc[i][j] = make_float4(0.f,0.f,0.f,0.f);

    auto issue = [&](int buf, int k0) {
        char* base = smem + buf * 32768;
        #pragma unroll
        for (int it = 0; it < 4; it++) {
            int cid = tid + 256 * it;
            int row = cid >> 3;
            int c   = cid & 7;
            int sw  = row * 128 + ((c ^ (row & 7)) << 4);
            cp16(base + sw,         A + (size_t)(m0 + row) * 1024 + k0 + c * 8);
            cp16(base + 16384 + sw, W + (size_t)(n0 + row) * 1024 + k0 + c * 8);
        }
    };

    const int NT = 1024 / 64;
    issue(0, 0);  cp_commit();
    issue(1, 64); cp_commit();

    for (int s = 0; s < NT; s++) {
        if (s + 2 < NT) issue((s + 2) % 3, (s + 2) * 64);
        cp_commit();
        cp_wait2();
        __syncthreads();

        const uint32_t As = sb + (s % 3) * 32768;
        const uint32_t Bs = As + 16384;

        #pragma unroll
        for (int ks = 0; ks < 4; ks++) {
            const int ch = ks * 2 + (lane >> 4);
            uint32_t af[2][4];
            #pragma unroll
            for (int i = 0; i < 2; i++) {
                int row = wm * 32 + i * 16 + (lane & 15);
                ldm_x4(af[i][0], af[i][1], af[i][2], af[i][3],
                       As + row * 128 + ((ch ^ (row & 7)) << 4));
            }
            uint32_t bf[8][2];
            #pragma unroll
            for (int jj = 0; jj < 4; jj++) {
                int row = wn * 64 + jj * 16 + (lane & 15);
                uint32_t r0, r1, r2, r3;
                ldm_x4(r0, r1, r2, r3, Bs + row * 128 + ((ch ^ (row & 7)) << 4));
                bf[2*jj][0]   = r0; bf[2*jj][1]   = r2;
                bf[2*jj+1][0] = r1; bf[2*jj+1][1] = r3;
            }
            #pragma unroll
            for (int i = 0; i < 2; i++)
                #pragma unroll
                for (int j = 0; j < 8; j++)
                    mma16(acc[i][j], af[i][0], af[i][1], af[i][2], af[i][3],
                          bf[j][0], bf[j][1]);
        }
        __syncthreads();
    }

    if (EPI == 0) {
        #pragma unroll
        for (int i = 0; i < 2; i++) {
            #pragma unroll
            for (int rh = 0; rh < 2; rh++) {
                int m = m0 + wm * 32 + 16 * i + g + rh * 8;
                int b_ = m >> 11;
                int s_ = m & (NS - 1);
                float pv = pad[b_ * NS + s_] ? 1.f : 0.f;
                #pragma unroll
                for (int j = 0; j < 8; j++) {
                    int c0 = n0 + wn * 64 + 8 * j + 2 * t;
                    float v0 = (rh ? acc[i][j].z : acc[i][j].x) + bias[c0];
                    float v1 = (rh ? acc[i][j].w : acc[i][j].y) + bias[c0 + 1];
                    int head = c0 / 192;
                    int rr = c0 - head * 192;
                    size_t base = ((size_t)(b_ * NH + head) * NS + s_) * NHD;
                    if (rr < 64)
                        *(__half2*)&g_Q[base + rr] =
                            __floats2half2_rn(v0 * QSCALE, v1 * QSCALE);
                    else if (rr < 128)
                        *(__half2*)&g_K[base + rr - 64] = __floats2half2_rn(v0, v1);
                    else
                        *(__half2*)&g_V[base + rr - 128] = __floats2half2_rn(v0 * pv, v1 * pv);
                }
            }
        }
    } else {
        #pragma unroll
        for (int i = 0; i < 2; i++) {
            int r0 = m0 + wm * 32 + 16 * i + g;
            int r1 = r0 + 8;
            #pragma unroll
            for (int j = 0; j < 8; j++) {
                int c0 = n0 + wn * 64 + 8 * j + 2 * t;
                float b0v = bias[c0], b1v = bias[c0 + 1];
                *(float2*)&C[(size_t)r0 * NDIM + c0] =
                    make_float2(acc[i][j].x + b0v, acc[i][j].y + b1v);
                *(float2*)&C[(size_t)r1 * NDIM + c0] =
                    make_float2(acc[i][j].z + b0v, acc[i][j].w + b1v);
            }
        }
    }
}

// ---------------------------------------------------------------------------
// Flash attention: fp16 mma, register-resident P, exp2 softmax (scale folded
// into Q). 128 threads, 64x64 tiles, 2 barriers per k-tile.
// V pad-folded; denominator unpadded; pad[q] at output.
// ---------------------------------------------------------------------------
__global__ void __launch_bounds__(128, 4)
flash_h(const int* __restrict__ pad, const int* __restrict__ amask)
{
    __shared__ char smem[3 * 8192];
    const uint32_t sb = (uint32_t)__cvta_generic_to_shared(smem);
    const uint32_t Qb = sb, Kb = sb + 8192, Vb = sb + 16384;

    const int tid = threadIdx.x;
    const int qt = gridDim.x - 1 - blockIdx.x;   // heavy CTAs first
    const int bh = blockIdx.y;
    const int b  = bh >> 4;
    const int h  = bh & 15;
    const int q0 = qt * 64;
    const int causal = amask ? (amask[0] != 0) : 1;

    const int warp = tid >> 5;
    const int lane = tid & 31;
    const int rbase = warp * 16;
    const int g = lane >> 2;
    const int t = lane & 3;

    // load Q tile [64][64] half, SW128 swizzle
    {
        const __half* Qg = g_Q + ((size_t)bh * NS + q0) * NHD;
        #pragma unroll
        for (int it = 0; it < 4; it++) {
            int cid = tid + 128 * it;
            int row = cid >> 3;
            int c   = cid & 7;
            int off = row * 128 + ((c ^ (row & 7)) << 4);
            *(float4*)(smem + off) = *(const float4*)(Qg + row * 64 + c * 8);
        }
    }

    float m0r = -1e30f, m1r = -1e30f, l0 = 0.f, l1 = 0.f;
    float4 accO[8];
    #pragma unroll
    for (int j = 0; j < 8; j++) accO[j] = make_float4(0.f,0.f,0.f,0.f);

    const int rowa = q0 + rbase + g;
    const int rowb = rowa + 8;
    const int ktmax = causal ? qt : (NS / 64 - 1);

    for (int kt = 0; kt <= ktmax; kt++) {
        const int k0 = kt * 64;
        __syncthreads();   // prior iter done reading K/V (covers Q load on iter 0)

        {
            const __half* Kg = g_K + ((size_t)bh * NS + k0) * NHD;
            const __half* Vg = g_V + ((size_t)bh * NS + k0) * NHD;
            #pragma unroll
            for (int it = 0; it < 4; it++) {
                int cid = tid + 128 * it;
                int row = cid >> 3;
                int c   = cid & 7;
                int off = row * 128 + ((c ^ (row & 7)) << 4);
                *(float4*)(smem + 8192 + off)  = *(const float4*)(Kg + row * 64 + c * 8);
                *(float4*)(smem + 16384 + off) = *(const float4*)(Vg + row * 64 + c * 8);
            }
        }
        __syncthreads();

        // S = Q @ K^T (scores already in log2 domain via Q pre-scale)
        float4 sfr[8];
        #pragma unroll
        for (int j = 0; j < 8; j++) sfr[j] = make_float4(0.f,0.f,0.f,0.f);
        #pragma unroll
        for (int ks = 0; ks < 4; ks++) {
            const int ch = ks * 2 + (lane >> 4);
            uint32_t a0, a1, a2, a3;
            {
                int row = rbase + (lane & 15);
                ldm_x4(a0, a1, a2, a3, Qb + row * 128 + ((ch ^ (row & 7)) << 4));
            }
            #pragma unroll
            for (int jj = 0; jj < 4; jj++) {
                int row = jj * 16 + (lane & 15);
                uint32_t r0, r1, r2, r3;
                ldm_x4(r0, r1, r2, r3, Kb + row * 128 + ((ch ^ (row & 7)) << 4));
                mma16(sfr[2*jj],   a0, a1, a2, a3, r0, r2);
                mma16(sfr[2*jj+1], a0, a1, a2, a3, r1, r3);
            }
        }

        // causal mask + online softmax (base-2)
        const bool diag = causal && (kt == qt);
        float mx0 = -1e30f, mx1 = -1e30f;
        #pragma unroll
        for (int j = 0; j < 8; j++) {
            if (diag) {
                int c0 = k0 + 8 * j + 2 * t;
                int c1 = c0 + 1;
                if (c0 > rowa) sfr[j].x = -1e30f;
                if (c1 > rowa) sfr[j].y = -1e30f;
                if (c0 > rowb) sfr[j].z = -1e30f;
                if (c1 > rowb) sfr[j].w = -1e30f;
            }
            mx0 = fmaxf(mx0, fmaxf(sfr[j].x, sfr[j].y));
            mx1 = fmaxf(mx1, fmaxf(sfr[j].z, sfr[j].w));
        }
        #pragma unroll
        for (int off = 1; off < 4; off <<= 1) {
            mx0 = fmaxf(mx0, __shfl_xor_sync(0xffffffffu, mx0, off));
            mx1 = fmaxf(mx1, __shfl_xor_sync(0xffffffffu, mx1, off));
        }
        float nm0 = fmaxf(m0r, mx0);
        float nm1 = fmaxf(m1r, mx1);
        float s0 = 0.f, s1 = 0.f;
        #pragma unroll
        for (int j = 0; j < 8; j++) {
            float px = ex2f(sfr[j].x - nm0);
            float py = ex2f(sfr[j].y - nm0);
            float pz = ex2f(sfr[j].z - nm1);
            float pw = ex2f(sfr[j].w - nm1);
            sfr[j] = make_float4(px, py, pz, pw);
            s0 += px + py;
            s1 += pz + pw;
        }
        #pragma unroll
        for (int off = 1; off < 4; off <<= 1) {
            s0 += __shfl_xor_sync(0xffffffffu, s0, off);
            s1 += __shfl_xor_sync(0xffffffffu, s1, off);
        }
        float al0 = ex2f(m0r - nm0);
        float al1 = ex2f(m1r - nm1);
        l0 = l0 * al0 + s0;  m0r = nm0;
        l1 = l1 * al1 + s1;  m1r = nm1;
        #pragma unroll
        for (int j = 0; j < 8; j++) {
            accO[j].x *= al0; accO[j].y *= al0;
            accO[j].z *= al1; accO[j].w *= al1;
        }

        // accO += P @ V — P stays in registers (S-accum layout == PV A-fragment)
        #pragma unroll
        for (int ks = 0; ks < 4; ks++) {
            uint32_t a0 = h2u(sfr[2*ks].x,   sfr[2*ks].y);
            uint32_t a1 = h2u(sfr[2*ks].z,   sfr[2*ks].w);
            uint32_t a2 = h2u(sfr[2*ks+1].x, sfr[2*ks+1].y);
            uint32_t a3 = h2u(sfr[2*ks+1].z, sfr[2*ks+1].w);
            #pragma unroll
            for (int jj = 0; jj < 4; jj++) {
                int kvrow = ks * 16 + (lane & 15);
                int dch = jj * 2 + (lane >> 4);
                uint32_t r0, r1, r2, r3;
                ldm_x4t(r0, r1, r2, r3, Vb + kvrow * 128 + ((dch ^ (kvrow & 7)) << 4));
                mma16(accO[2*jj],   a0, a1, a2, a3, r0, r1);
                mma16(accO[2*jj+1], a0, a1, a2, a3, r2, r3);
            }
        }
    }

    // finalize: /l, pad[q], store half ctx
    float pq0 = pad[b * NS + rowa] ? 1.f : 0.f;
    float pq1 = pad[b * NS + rowb] ? 1.f : 0.f;
    float inv0 = pq0 / l0;
    float inv1 = pq1 / l1;
    #pragma unroll
    for (int j = 0; j < 8; j++) {
        int col = h * 64 + 8 * j + 2 * t;
        *(__half2*)&g_ctx[((size_t)b * NS + rowa) * ND + col] =
            __floats2half2_rn(accO[j].x * inv0, accO[j].y * inv0);
        *(__half2*)&g_ctx[((size_t)b * NS + rowb) * ND + col] =
            __floats2half2_rn(accO[j].z * inv1, accO[j].w * inv1);
    }
}

// ---------------------------------------------------------------------------
extern "C" void kernel_launch(void* const* d_in, const int* in_sizes, int n_in,
                              void* d_out, int out_size)
{
    const float* x    = (const float*)d_in[0];
    const int*   pad  = (const int*)d_in[1];
    const float* Wqkv = (const float*)d_in[2];
    const float* bqkv = (const float*)d_in[3];
    const float* Wo   = (const float*)d_in[4];
    const float* bo   = (const float*)d_in[5];
    const int*   am   = (n_in > 6) ? (const int*)d_in[6] : nullptr;

    __half *xh, *wqkvh, *woh, *ctx;
    cudaGetSymbolAddress((void**)&xh,    g_xh);
    cudaGetSymbolAddress((void**)&wqkvh, g_wqkvh);
    cudaGetSymbolAddress((void**)&woh,   g_woh);
    cudaGetSymbolAddress((void**)&ctx,   g_ctx);

    const int GEMM_SMEM = 3 * 32768;
    cudaFuncSetAttribute(hgemm<0, 3*ND>, cudaFuncAttributeMaxDynamicSharedMemorySize, GEMM_SMEM);
    cudaFuncSetAttribute(hgemm<1, ND>,   cudaFuncAttributeMaxDynamicSharedMemorySize, GEMM_SMEM);

    // 0) fp16 conversion prepass
    {
        int n;
        n = NB*NS*ND/4;  f2h_k<<<(n+255)/256, 256>>>(x, xh, n);
        n = 3*ND*ND/4;   f2h_k<<<(n+255)/256, 256>>>(Wqkv, wqkvh, n);
        n = ND*ND/4;     f2h_k<<<(n+255)/256, 256>>>(Wo, woh, n);
    }

    // 1) QKV projection + scatter (Q pre-scaled, V pad-folded)
    dim3 g1(3*ND/128, (NB*NS)/128);
    hgemm<0, 3*ND><<<g1, 256, GEMM_SMEM>>>(xh, wqkvh, bqkv, nullptr, pad);

    // 2) flash attention
    dim3 g2(NS/64, NB*NH);
    flash_h<<<g2, 128>>>(pad, am);

    // 3) output projection
    dim3 g3(ND/128, (NB*NS)/128);
    hgemm<1, ND><<<g3, 256, GEMM_SMEM>>>(ctx, woh, bo, (float*)d_out, nullptr);
}

// round 6
// speedup vs baseline: 7.9152x; 1.0450x over previous
#include <cuda_runtime.h>
#include <cuda_fp16.h>
#include <cstdint>

#define NB 4
#define NS 2048
#define ND 1024
#define NH 16
#define NHD 64

// Scratch (device globals — allocation-free rule)
__device__ __half g_Q[NB*NH*NS*NHD];     // pre-scaled by 0.125*log2(e)
__device__ __half g_K[NB*NH*NS*NHD];
__device__ __half g_V[NB*NH*NS*NHD];     // pad[k] pre-folded
__device__ __half g_ctx[NB*NS*ND];
__device__ __half g_xh[NB*NS*ND];
__device__ __half g_wqkvh[3*ND*ND];
__device__ __half g_woh[ND*ND];

#define QSCALE 0.1803368801111137f   // 0.125 * log2(e)

// ---------------------------------------------------------------------------
// helpers
// ---------------------------------------------------------------------------
__device__ __forceinline__ void mma16(float4& d,
                                      uint32_t a0, uint32_t a1, uint32_t a2, uint32_t a3,
                                      uint32_t b0, uint32_t b1) {
    asm volatile("mma.sync.aligned.m16n8k16.row.col.f32.f16.f16.f32 "
                 "{%0,%1,%2,%3}, {%4,%5,%6,%7}, {%8,%9}, {%0,%1,%2,%3};"
                 : "+f"(d.x), "+f"(d.y), "+f"(d.z), "+f"(d.w)
                 : "r"(a0), "r"(a1), "r"(a2), "r"(a3), "r"(b0), "r"(b1));
}

__device__ __forceinline__ void ldm_x4(uint32_t& r0, uint32_t& r1, uint32_t& r2, uint32_t& r3,
                                       uint32_t addr) {
    asm volatile("ldmatrix.sync.aligned.m8n8.x4.shared.b16 {%0,%1,%2,%3}, [%4];"
                 : "=r"(r0), "=r"(r1), "=r"(r2), "=r"(r3) : "r"(addr));
}

__device__ __forceinline__ void ldm_x4t(uint32_t& r0, uint32_t& r1, uint32_t& r2, uint32_t& r3,
                                        uint32_t addr) {
    asm volatile("ldmatrix.sync.aligned.m8n8.x4.trans.shared.b16 {%0,%1,%2,%3}, [%4];"
                 : "=r"(r0), "=r"(r1), "=r"(r2), "=r"(r3) : "r"(addr));
}

__device__ __forceinline__ void cp16(void* s, const void* g) {
    uint32_t sa = (uint32_t)__cvta_generic_to_shared(s);
    asm volatile("cp.async.cg.shared.global [%0], [%1], 16;" :: "r"(sa), "l"(g) : "memory");
}
__device__ __forceinline__ void cp16s(uint32_t sa, const void* g) {
    asm volatile("cp.async.cg.shared.global [%0], [%1], 16;" :: "r"(sa), "l"(g) : "memory");
}
__device__ __forceinline__ void cp_commit() { asm volatile("cp.async.commit_group;" ::: "memory"); }
__device__ __forceinline__ void cp_wait2()  { asm volatile("cp.async.wait_group 2;" ::: "memory"); }
__device__ __forceinline__ void cp_wait1()  { asm volatile("cp.async.wait_group 1;" ::: "memory"); }

__device__ __forceinline__ float ex2f(float x) {
    float y;
    asm("ex2.approx.ftz.f32 %0, %1;" : "=f"(y) : "f"(x));
    return y;
}

__device__ __forceinline__ uint32_t h2u(float a, float b) {
    __half2 h = __floats2half2_rn(a, b);
    return *(uint32_t*)&h;
}

// ---------------------------------------------------------------------------
// fp32 -> fp16 prepass
// ---------------------------------------------------------------------------
__global__ void f2h_k(const float* __restrict__ in, __half* __restrict__ out, int n4) {
    int i = blockIdx.x * blockDim.x + threadIdx.x;
    if (i < n4) {
        float4 v = ((const float4*)in)[i];
        ((__half2*)out)[i*2]   = __floats2half2_rn(v.x, v.y);
        ((__half2*)out)[i*2+1] = __floats2half2_rn(v.z, v.w);
    }
}

// ---------------------------------------------------------------------------
// fp16 mma GEMM (NT) — unchanged from round 5 (known good)
// ---------------------------------------------------------------------------
template<int EPI, int NDIM>
__global__ void __launch_bounds__(256, 2)
hgemm(const __half* __restrict__ A, const __half* __restrict__ W,
      const float* __restrict__ bias, float* __restrict__ C,
      const int* __restrict__ pad)
{
    extern __shared__ char smem[];
    const uint32_t sb = (uint32_t)__cvta_generic_to_shared(smem);

    const int tid  = threadIdx.x;
    const int warp = tid >> 5;
    const int lane = tid & 31;
    const int m0 = blockIdx.y * 128;
    const int n0 = blockIdx.x * 128;
    const int wm = warp >> 1;
    const int wn = warp & 1;
    const int g = lane >> 2;
    const int t = lane & 3;

    float4 acc[2][8];
    #pragma unroll
    for (int i = 0; i < 2; i++)
        #pragma unroll
        for (int j = 0; j < 8; j++) acc[i][j] = make_float4(0.f,0.f,0.f,0.f);

    auto issue = [&](int buf, int k0) {
        char* base = smem + buf * 32768;
        #pragma unroll
        for (int it = 0; it < 4; it++) {
            int cid = tid + 256 * it;
            int row = cid >> 3;
            int c   = cid & 7;
            int sw  = row * 128 + ((c ^ (row & 7)) << 4);
            cp16(base + sw,         A + (size_t)(m0 + row) * 1024 + k0 + c * 8);
            cp16(base + 16384 + sw, W + (size_t)(n0 + row) * 1024 + k0 + c * 8);
        }
    };

    const int NT = 1024 / 64;
    issue(0, 0);  cp_commit();
    issue(1, 64); cp_commit();

    for (int s = 0; s < NT; s++) {
        if (s + 2 < NT) issue((s + 2) % 3, (s + 2) * 64);
        cp_commit();
        cp_wait2();
        __syncthreads();

        const uint32_t As = sb + (s % 3) * 32768;
        const uint32_t Bs = As + 16384;

        #pragma unroll
        for (int ks = 0; ks < 4; ks++) {
            const int ch = ks * 2 + (lane >> 4);
            uint32_t af[2][4];
            #pragma unroll
            for (int i = 0; i < 2; i++) {
                int row = wm * 32 + i * 16 + (lane & 15);
                ldm_x4(af[i][0], af[i][1], af[i][2], af[i][3],
                       As + row * 128 + ((ch ^ (row & 7)) << 4));
            }
            uint32_t bf[8][2];
            #pragma unroll
            for (int jj = 0; jj < 4; jj++) {
                int row = wn * 64 + jj * 16 + (lane & 15);
                uint32_t r0, r1, r2, r3;
                ldm_x4(r0, r1, r2, r3, Bs + row * 128 + ((ch ^ (row & 7)) << 4));
                bf[2*jj][0]   = r0; bf[2*jj][1]   = r2;
                bf[2*jj+1][0] = r1; bf[2*jj+1][1] = r3;
            }
            #pragma unroll
            for (int i = 0; i < 2; i++)
                #pragma unroll
                for (int j = 0; j < 8; j++)
                    mma16(acc[i][j], af[i][0], af[i][1], af[i][2], af[i][3],
                          bf[j][0], bf[j][1]);
        }
        __syncthreads();
    }

    if (EPI == 0) {
        #pragma unroll
        for (int i = 0; i < 2; i++) {
            #pragma unroll
            for (int rh = 0; rh < 2; rh++) {
                int m = m0 + wm * 32 + 16 * i + g + rh * 8;
                int b_ = m >> 11;
                int s_ = m & (NS - 1);
                float pv = pad[b_ * NS + s_] ? 1.f : 0.f;
                #pragma unroll
                for (int j = 0; j < 8; j++) {
                    int c0 = n0 + wn * 64 + 8 * j + 2 * t;
                    float v0 = (rh ? acc[i][j].z : acc[i][j].x) + bias[c0];
                    float v1 = (rh ? acc[i][j].w : acc[i][j].y) + bias[c0 + 1];
                    int head = c0 / 192;
                    int rr = c0 - head * 192;
                    size_t base = ((size_t)(b_ * NH + head) * NS + s_) * NHD;
                    if (rr < 64)
                        *(__half2*)&g_Q[base + rr] =
                            __floats2half2_rn(v0 * QSCALE, v1 * QSCALE);
                    else if (rr < 128)
                        *(__half2*)&g_K[base + rr - 64] = __floats2half2_rn(v0, v1);
                    else
                        *(__half2*)&g_V[base + rr - 128] = __floats2half2_rn(v0 * pv, v1 * pv);
                }
            }
        }
    } else {
        #pragma unroll
        for (int i = 0; i < 2; i++) {
            int r0 = m0 + wm * 32 + 16 * i + g;
            int r1 = r0 + 8;
            #pragma unroll
            for (int j = 0; j < 8; j++) {
                int c0 = n0 + wn * 64 + 8 * j + 2 * t;
                float b0v = bias[c0], b1v = bias[c0 + 1];
                *(float2*)&C[(size_t)r0 * NDIM + c0] =
                    make_float2(acc[i][j].x + b0v, acc[i][j].y + b1v);
                *(float2*)&C[(size_t)r1 * NDIM + c0] =
                    make_float2(acc[i][j].z + b0v, acc[i][j].w + b1v);
            }
        }
    }
}

// ---------------------------------------------------------------------------
// Flash attention v3: 128-row Q tile, 8 warps (256 thr), cp.async
// double-buffered K/V, register-resident P, exp2 softmax, dead-tile skip.
// V pad-folded; denominator unpadded; pad[q] at output.
// ---------------------------------------------------------------------------
__global__ void __launch_bounds__(256, 2)
flash_h(const int* __restrict__ pad, const int* __restrict__ amask)
{
    __shared__ char smem[16384 + 2*8192 + 2*8192];   // Q | K0 K1 | V0 V1 (48KB)
    const uint32_t sb = (uint32_t)__cvta_generic_to_shared(smem);
    const uint32_t Qb = sb;

    const int tid = threadIdx.x;
    const int qt = gridDim.x - 1 - blockIdx.x;   // heavy CTAs first
    const int bh = blockIdx.y;
    const int b  = bh >> 4;
    const int h  = bh & 15;
    const int q0 = qt * 128;
    const int causal = amask ? (amask[0] != 0) : 1;

    const int warp = tid >> 5;
    const int lane = tid & 31;
    const int rbase = warp * 16;
    const int g = lane >> 4 ? (lane & 31) >> 2 : lane >> 2;  // = (lane>>2)&7? no:
    const int gq = lane >> 2;       // quad row 0..7
    const int t = lane & 3;

    // cp.async Q tile [128][64] half (16KB)
    {
        const __half* Qg = g_Q + ((size_t)bh * NS + q0) * NHD;
        #pragma unroll
        for (int it = 0; it < 4; it++) {
            int cid = tid + 256 * it;       // 0..1023
            int row = cid >> 3;             // 0..127
            int c   = cid & 7;
            cp16s(Qb + row * 128 + ((c ^ (row & 7)) << 4), Qg + row * 64 + c * 8);
        }
    }
    cp_commit();

    const int ktmax = causal ? (2 * qt + 1) : (NS / 64 - 1);

    auto issue_kv = [&](int buf, int k0) {
        const __half* Kg = g_K + ((size_t)bh * NS + k0) * NHD;
        const __half* Vg = g_V + ((size_t)bh * NS + k0) * NHD;
        uint32_t Kb = sb + 16384 + buf * 8192;
        uint32_t Vb = sb + 32768 + buf * 8192;
        #pragma unroll
        for (int it = 0; it < 2; it++) {
            int cid = tid + 256 * it;       // 0..511
            int row = cid >> 3;             // 0..63
            int c   = cid & 7;
            int off = row * 128 + ((c ^ (row & 7)) << 4);
            cp16s(Kb + off, Kg + row * 64 + c * 8);
            cp16s(Vb + off, Vg + row * 64 + c * 8);
        }
    };

    issue_kv(0, 0);
    cp_commit();

    float m0r = -1e30f, m1r = -1e30f, l0 = 0.f, l1 = 0.f;
    float4 accO[8];
    #pragma unroll
    for (int j = 0; j < 8; j++) accO[j] = make_float4(0.f,0.f,0.f,0.f);

    const int rowa = q0 + rbase + gq;
    const int rowb = rowa + 8;
    const int rowmax = q0 + rbase + 15;

    for (int kt = 0; kt <= ktmax; kt++) {
        const int k0 = kt * 64;
        // prefetch next tile (other buffer — safe: last read 2 iters ago,
        // protected by trailing barrier of previous iteration)
        if (kt + 1 <= ktmax) issue_kv((kt + 1) & 1, (kt + 1) * 64);
        cp_commit();
        cp_wait1();          // tile kt (and Q) arrived
        __syncthreads();

        const uint32_t Kb = sb + 16384 + (kt & 1) * 8192;
        const uint32_t Vb = sb + 32768 + (kt & 1) * 8192;

        // dead-tile skip: all rows of this warp above diagonal -> P == 0
        if (!causal || k0 <= rowmax) {
            // S = Q @ K^T (log2 domain via Q pre-scale)
            float4 sfr[8];
            #pragma unroll
            for (int j = 0; j < 8; j++) sfr[j] = make_float4(0.f,0.f,0.f,0.f);
            #pragma unroll
            for (int ks = 0; ks < 4; ks++) {
                const int ch = ks * 2 + (lane >> 4);
                uint32_t a0, a1, a2, a3;
                {
                    int row = rbase + (lane & 15);
                    ldm_x4(a0, a1, a2, a3, Qb + row * 128 + ((ch ^ (row & 7)) << 4));
                }
                #pragma unroll
                for (int jj = 0; jj < 4; jj++) {
                    int row = jj * 16 + (lane & 15);
                    uint32_t r0, r1, r2, r3;
                    ldm_x4(r0, r1, r2, r3, Kb + row * 128 + ((ch ^ (row & 7)) << 4));
                    mma16(sfr[2*jj],   a0, a1, a2, a3, r0, r2);
                    mma16(sfr[2*jj+1], a0, a1, a2, a3, r1, r3);
                }
            }

            // causal mask + online softmax (base-2)
            const bool diag = causal && (k0 + 63 > q0 + rbase);
            float mx0 = -1e30f, mx1 = -1e30f;
            #pragma unroll
            for (int j = 0; j < 8; j++) {
                if (diag) {
                    int c0 = k0 + 8 * j + 2 * t;
                    int c1 = c0 + 1;
                    if (c0 > rowa) sfr[j].x = -1e30f;
                    if (c1 > rowa) sfr[j].y = -1e30f;
                    if (c0 > rowb) sfr[j].z = -1e30f;
                    if (c1 > rowb) sfr[j].w = -1e30f;
                }
                mx0 = fmaxf(mx0, fmaxf(sfr[j].x, sfr[j].y));
                mx1 = fmaxf(mx1, fmaxf(sfr[j].z, sfr[j].w));
            }
            #pragma unroll
            for (int off = 1; off < 4; off <<= 1) {
                mx0 = fmaxf(mx0, __shfl_xor_sync(0xffffffffu, mx0, off));
                mx1 = fmaxf(mx1, __shfl_xor_sync(0xffffffffu, mx1, off));
            }
            float nm0 = fmaxf(m0r, mx0);
            float nm1 = fmaxf(m1r, mx1);
            float s0 = 0.f, s1 = 0.f;
            #pragma unroll
            for (int j = 0; j < 8; j++) {
                float px = ex2f(sfr[j].x - nm0);
                float py = ex2f(sfr[j].y - nm0);
                float pz = ex2f(sfr[j].z - nm1);
                float pw = ex2f(sfr[j].w - nm1);
                sfr[j] = make_float4(px, py, pz, pw);
                s0 += px + py;
                s1 += pz + pw;
            }
            #pragma unroll
            for (int off = 1; off < 4; off <<= 1) {
                s0 += __shfl_xor_sync(0xffffffffu, s0, off);
                s1 += __shfl_xor_sync(0xffffffffu, s1, off);
            }
            float al0 = ex2f(m0r - nm0);
            float al1 = ex2f(m1r - nm1);
            l0 = l0 * al0 + s0;  m0r = nm0;
            l1 = l1 * al1 + s1;  m1r = nm1;
            #pragma unroll
            for (int j = 0; j < 8; j++) {
                accO[j].x *= al0; accO[j].y *= al0;
                accO[j].z *= al1; accO[j].w *= al1;
            }

            // accO += P @ V — P stays in registers
            #pragma unroll
            for (int ks = 0; ks < 4; ks++) {
                uint32_t a0 = h2u(sfr[2*ks].x,   sfr[2*ks].y);
                uint32_t a1 = h2u(sfr[2*ks].z,   sfr[2*ks].w);
                uint32_t a2 = h2u(sfr[2*ks+1].x, sfr[2*ks+1].y);
                uint32_t a3 = h2u(sfr[2*ks+1].z, sfr[2*ks+1].w);
                #pragma unroll
                for (int jj = 0; jj < 4; jj++) {
                    int kvrow = ks * 16 + (lane & 15);
                    int dch = jj * 2 + (lane >> 4);
                    uint32_t r0, r1, r2, r3;
                    ldm_x4t(r0, r1, r2, r3, Vb + kvrow * 128 + ((dch ^ (kvrow & 7)) << 4));
                    mma16(accO[2*jj],   a0, a1, a2, a3, r0, r1);
                    mma16(accO[2*jj+1], a0, a1, a2, a3, r2, r3);
                }
            }
        }
        __syncthreads();   // all warps done with buffers before next prefetch reuses
    }

    // finalize: /l, pad[q], store half ctx
    float pq0 = pad[b * NS + rowa] ? 1.f : 0.f;
    float pq1 = pad[b * NS + rowb] ? 1.f : 0.f;
    float inv0 = pq0 / l0;
    float inv1 = pq1 / l1;
    #pragma unroll
    for (int j = 0; j < 8; j++) {
        int col = h * 64 + 8 * j + 2 * t;
        *(__half2*)&g_ctx[((size_t)b * NS + rowa) * ND + col] =
            __floats2half2_rn(accO[j].x * inv0, accO[j].y * inv0);
        *(__half2*)&g_ctx[((size_t)b * NS + rowb) * ND + col] =
            __floats2half2_rn(accO[j].z * inv1, accO[j].w * inv1);
    }
}

// ---------------------------------------------------------------------------
extern "C" void kernel_launch(void* const* d_in, const int* in_sizes, int n_in,
                              void* d_out, int out_size)
{
    const float* x    = (const float*)d_in[0];
    const int*   pad  = (const int*)d_in[1];
    const float* Wqkv = (const float*)d_in[2];
    const float* bqkv = (const float*)d_in[3];
    const float* Wo   = (const float*)d_in[4];
    const float* bo   = (const float*)d_in[5];
    const int*   am   = (n_in > 6) ? (const int*)d_in[6] : nullptr;

    __half *xh, *wqkvh, *woh, *ctx;
    cudaGetSymbolAddress((void**)&xh,    g_xh);
    cudaGetSymbolAddress((void**)&wqkvh, g_wqkvh);
    cudaGetSymbolAddress((void**)&woh,   g_woh);
    cudaGetSymbolAddress((void**)&ctx,   g_ctx);

    const int GEMM_SMEM = 3 * 32768;
    cudaFuncSetAttribute(hgemm<0, 3*ND>, cudaFuncAttributeMaxDynamicSharedMemorySize, GEMM_SMEM);
    cudaFuncSetAttribute(hgemm<1, ND>,   cudaFuncAttributeMaxDynamicSharedMemorySize, GEMM_SMEM);

    // 0) fp16 conversion prepass
    {
        int n;
        n = NB*NS*ND/4;  f2h_k<<<(n+255)/256, 256>>>(x, xh, n);
        n = 3*ND*ND/4;   f2h_k<<<(n+255)/256, 256>>>(Wqkv, wqkvh, n);
        n = ND*ND/4;     f2h_k<<<(n+255)/256, 256>>>(Wo, woh, n);
    }

    // 1) QKV projection + scatter (Q pre-scaled, V pad-folded)
    dim3 g1(3*ND/128, (NB*NS)/128);
    hgemm<0, 3*ND><<<g1, 256, GEMM_SMEM>>>(xh, wqkvh, bqkv, nullptr, pad);

    // 2) flash attention (128-row Q tiles)
    dim3 g2(NS/128, NB*NH);           // (16, 64)
    flash_h<<<g2, 256>>>(pad, am);

    // 3) output projection
    dim3 g3(ND/128, (NB*NS)/128);
    hgemm<1, ND><<<g3, 256, GEMM_SMEM>>>(ctx, woh, bo, (float*)d_out, nullptr);
}